// round 1
// baseline (speedup 1.0000x reference)
#include <cuda_runtime.h>
#include <math.h>

// ---------------------------------------------------------------------------
// ContextualAttention: B=2, C=128, H=W=128, RATE=2, BLOCK=3, SCALE=10, EPS=1e-4
//
// Pipeline (all fp32):
//   Xr[b][c][p]        = x[b,c,2py,2px]                              (c,p) layout
//   G  = Xr^T Xr       (L x L, K=128)  Gram of strided pixels
//   att_raw[p,q]       = sum_{d in 3x3} G[p+d, q+d]   (zero-pad valid mask)
//   denom_p            = sqrt(att_raw[p,p] + 1152*EPS)
//   s[p,q]             = mfilt_p * 10 * att_raw[p,q] / denom_p
//   att = softmax over p (per column q), then row-masked by mfilt_p
//   Vt[b][f][p]        = x[b,c,2py-1+i,2px-1+j], f = c*16+i*4+j      (f,p) layout
//   M2[f,q]            = sum_p Vt[f,p] * att[p,q]
//   out[c,Y,X]         = 0.25 * sum over <=4 (qy,i),(qx,j) of M2[(c,i,j), q]
// ---------------------------------------------------------------------------

constexpr int Bn = 2, Cn = 128, Hn = 128, Wn = 128;
constexpr int HR = 64, Ln = 4096, F2 = 2048, KC = 128;
constexpr int PCH = 8;                 // p-chunks for partial softmax
constexpr int PCS = Ln / PCH;          // 512

// -------- static scratch (allocation-free rule) ----------------------------
__device__ float g_Xr[Bn][KC][Ln];     //   4 MB
__device__ float g_Vt[Bn][F2][Ln];     //  67 MB
__device__ float g_G [Bn][Ln][Ln];     // 134 MB
__device__ float g_S [Bn][Ln][Ln];     // 134 MB
__device__ float g_M2[Bn][F2][Ln];     //  67 MB
__device__ float g_invd [Bn][Ln];
__device__ float g_mfilt[Bn][Ln];
__device__ float g_pmax[Bn][PCH][Ln];
__device__ float g_psum[Bn][PCH][Ln];
__device__ float g_cmax[Bn][Ln];
__device__ float g_crcp[Bn][Ln];

// ---------------------------------------------------------------------------
__global__ void k_build_xr(const float* __restrict__ x) {
    int idx = blockIdx.x * blockDim.x + threadIdx.x;
    if (idx >= Bn * KC * Ln) return;
    int p = idx & (Ln - 1);
    int c = (idx >> 12) & (KC - 1);
    int b = idx >> 19;
    int py = p >> 6, px = p & 63;
    g_Xr[b][c][p] = x[((b * Cn + c) * Hn + 2 * py) * Wn + 2 * px];
}

__global__ void k_build_vt(const float* __restrict__ x) {
    int idx = blockIdx.x * blockDim.x + threadIdx.x;
    if (idx >= Bn * F2 * Ln) return;
    int p = idx & (Ln - 1);
    int f = (idx >> 12) & (F2 - 1);
    int b = idx >> 23;
    int c = f >> 4, i = (f >> 2) & 3, j = f & 3;
    int py = p >> 6, px = p & 63;
    int r  = 2 * py - 1 + i;
    int cc = 2 * px - 1 + j;
    float v = 0.0f;
    if (r >= 0 && r < Hn && cc >= 0 && cc < Wn)
        v = x[((b * Cn + c) * Hn + r) * Wn + cc];
    g_Vt[b][f][p] = v;
}

__global__ void k_mfilt(const float* __restrict__ mask) {
    int idx = blockIdx.x * blockDim.x + threadIdx.x;
    if (idx >= Bn * Ln) return;
    int q = idx & (Ln - 1);
    int b = idx >> 12;
    int qy = q >> 6, qx = q & 63;
    float s = 0.0f;
    #pragma unroll
    for (int dy = -1; dy <= 1; dy++)
        #pragma unroll
        for (int dx = -1; dx <= 1; dx++) {
            int yy = qy + dy, xx = qx + dx;
            if (yy >= 0 && yy < HR && xx >= 0 && xx < HR)
                s += mask[(b * Hn + 2 * yy) * Wn + 2 * xx];
        }
    g_mfilt[b][q] = ((s / 9.0f) == 0.0f) ? 1.0f : 0.0f;
}

// -------- GEMM 1: G = Xr^T * Xr  (both operands k-major, K=128) ------------
__global__ void __launch_bounds__(256) k_gemm_G() {
    int b  = blockIdx.z;
    int m0 = blockIdx.y << 7, n0 = blockIdx.x << 7;
    __shared__ float As[8][128];
    __shared__ float Bs[8][128];
    int tid = threadIdx.x, ty = tid >> 4, tx = tid & 15;
    int lk = tid >> 5, ls = (tid & 31) << 2;
    const float* A = &g_Xr[b][0][0];

    float acc[8][8];
    #pragma unroll
    for (int i = 0; i < 8; i++)
        #pragma unroll
        for (int j = 0; j < 8; j++) acc[i][j] = 0.0f;

    for (int k0 = 0; k0 < KC; k0 += 8) {
        *(float4*)&As[lk][ls] = *(const float4*)&A[(k0 + lk) * Ln + m0 + ls];
        *(float4*)&Bs[lk][ls] = *(const float4*)&A[(k0 + lk) * Ln + n0 + ls];
        __syncthreads();
        #pragma unroll
        for (int kk = 0; kk < 8; kk++) {
            float a[8], bb[8];
            *(float4*)&a[0]  = *(float4*)&As[kk][ty << 2];
            *(float4*)&a[4]  = *(float4*)&As[kk][64 + (ty << 2)];
            *(float4*)&bb[0] = *(float4*)&Bs[kk][tx << 2];
            *(float4*)&bb[4] = *(float4*)&Bs[kk][64 + (tx << 2)];
            #pragma unroll
            for (int i = 0; i < 8; i++)
                #pragma unroll
                for (int j = 0; j < 8; j++) acc[i][j] += a[i] * bb[j];
        }
        __syncthreads();
    }
    #pragma unroll
    for (int i = 0; i < 8; i++) {
        int m = m0 + ((i < 4) ? (ty << 2) + i : 64 + (ty << 2) + i - 4);
        float4 c0 = make_float4(acc[i][0], acc[i][1], acc[i][2], acc[i][3]);
        float4 c1 = make_float4(acc[i][4], acc[i][5], acc[i][6], acc[i][7]);
        *(float4*)&g_G[b][m][n0 + (tx << 2)]      = c0;
        *(float4*)&g_G[b][m][n0 + 64 + (tx << 2)] = c1;
    }
}

// -------- denom from diag of shifted G -------------------------------------
__global__ void k_diag() {
    int idx = blockIdx.x * blockDim.x + threadIdx.x;
    if (idx >= Bn * Ln) return;
    int p = idx & (Ln - 1);
    int b = idx >> 12;
    int py = p >> 6, px = p & 63;
    float acc = 0.0f;
    #pragma unroll
    for (int dy = -1; dy <= 1; dy++)
        #pragma unroll
        for (int dx = -1; dx <= 1; dx++) {
            int yy = py + dy, xx = px + dx;
            if (yy >= 0 && yy < HR && xx >= 0 && xx < HR) {
                int u = (yy << 6) + xx;
                acc += g_G[b][u][u];
            }
        }
    g_invd[b][p] = 10.0f / sqrtf(acc + 0.1152f);   // 1152 * 1e-4
}

// -------- scores: 9-tap diagonal shift-sum of G ----------------------------
__global__ void k_scores() {
    int b = blockIdx.z;
    int p = blockIdx.y;
    int q = (blockIdx.x << 8) + threadIdx.x;
    int py = p >> 6, px = p & 63;
    int qy = q >> 6, qx = q & 63;
    float acc = 0.0f;
    #pragma unroll
    for (int dy = -1; dy <= 1; dy++)
        #pragma unroll
        for (int dx = -1; dx <= 1; dx++) {
            bool ok = (py + dy >= 0) && (py + dy < HR) && (px + dx >= 0) && (px + dx < HR)
                   && (qy + dy >= 0) && (qy + dy < HR) && (qx + dx >= 0) && (qx + dx < HR);
            if (ok) {
                int off = dy * 64 + dx;
                acc += g_G[b][p + off][q + off];
            }
        }
    g_S[b][p][q] = g_mfilt[b][p] * g_invd[b][p] * acc;
}

// -------- softmax over p (columns), chunked --------------------------------
__global__ void k_soft1() {
    int b = blockIdx.z;
    int q = (blockIdx.x << 8) + threadIdx.x;
    int p0 = blockIdx.y * PCS;
    float m = -3.0e38f;
    for (int p = p0; p < p0 + PCS; p++) m = fmaxf(m, g_S[b][p][q]);
    float s = 0.0f;
    for (int p = p0; p < p0 + PCS; p++) {
        float d = g_S[b][p][q] - m;
        if (d > -21.0f) s += __expf(d);   // exp(-21) ~ 7.6e-10: negligible mass
    }
    g_pmax[b][blockIdx.y][q] = m;
    g_psum[b][blockIdx.y][q] = s;
}

__global__ void k_soft2() {
    int idx = blockIdx.x * blockDim.x + threadIdx.x;
    if (idx >= Bn * Ln) return;
    int q = idx & (Ln - 1);
    int b = idx >> 12;
    float m = -3.0e38f;
    #pragma unroll
    for (int ch = 0; ch < PCH; ch++) m = fmaxf(m, g_pmax[b][ch][q]);
    float s = 0.0f;
    #pragma unroll
    for (int ch = 0; ch < PCH; ch++) s += g_psum[b][ch][q] * __expf(g_pmax[b][ch][q] - m);
    g_cmax[b][q] = m;
    g_crcp[b][q] = 1.0f / s;
}

__global__ void k_soft3() {
    int b = blockIdx.z;
    int p = blockIdx.y;
    int q = (blockIdx.x << 8) + threadIdx.x;
    float d = g_S[b][p][q] - g_cmax[b][q];
    float w = 0.0f;
    if (d > -21.0f) w = __expf(d) * g_crcp[b][q];
    g_S[b][p][q] = w * g_mfilt[b][p];
}

// -------- GEMM 2: M2 = Vt * att  (M=2048, N=4096, K=4096) ------------------
__global__ void __launch_bounds__(256) k_gemm2() {
    int b  = blockIdx.z;
    int m0 = blockIdx.y << 7, n0 = blockIdx.x << 7;
    __shared__ float As[16][128];
    __shared__ float Bs[16][128];
    int tid = threadIdx.x, ty = tid >> 4, tx = tid & 15;
    const float* A  = &g_Vt[b][0][0];   // (M,K) row-major
    const float* Bp = &g_S [b][0][0];   // (K,N) row-major

    float acc[8][8];
    #pragma unroll
    for (int i = 0; i < 8; i++)
        #pragma unroll
        for (int j = 0; j < 8; j++) acc[i][j] = 0.0f;

    for (int k0 = 0; k0 < Ln; k0 += 16) {
        #pragma unroll
        for (int r = 0; r < 2; r++) {
            int idx = tid + r * 256;
            int ma = idx >> 2, ks = (idx & 3) << 2;
            float4 va = *(const float4*)&A[(m0 + ma) * Ln + k0 + ks];
            As[ks + 0][ma] = va.x;
            As[ks + 1][ma] = va.y;
            As[ks + 2][ma] = va.z;
            As[ks + 3][ma] = va.w;
            int kb = idx >> 5, ns = (idx & 31) << 2;
            *(float4*)&Bs[kb][ns] = *(const float4*)&Bp[(k0 + kb) * Ln + n0 + ns];
        }
        __syncthreads();
        #pragma unroll
        for (int kk = 0; kk < 16; kk++) {
            float a[8], bb[8];
            *(float4*)&a[0]  = *(float4*)&As[kk][ty << 2];
            *(float4*)&a[4]  = *(float4*)&As[kk][64 + (ty << 2)];
            *(float4*)&bb[0] = *(float4*)&Bs[kk][tx << 2];
            *(float4*)&bb[4] = *(float4*)&Bs[kk][64 + (tx << 2)];
            #pragma unroll
            for (int i = 0; i < 8; i++)
                #pragma unroll
                for (int j = 0; j < 8; j++) acc[i][j] += a[i] * bb[j];
        }
        __syncthreads();
    }
    #pragma unroll
    for (int i = 0; i < 8; i++) {
        int m = m0 + ((i < 4) ? (ty << 2) + i : 64 + (ty << 2) + i - 4);
        float4 c0 = make_float4(acc[i][0], acc[i][1], acc[i][2], acc[i][3]);
        float4 c1 = make_float4(acc[i][4], acc[i][5], acc[i][6], acc[i][7]);
        *(float4*)&g_M2[b][m][n0 + (tx << 2)]      = c0;
        *(float4*)&g_M2[b][m][n0 + 64 + (tx << 2)] = c1;
    }
}

// -------- overlap-add (transposed-conv scatter, gathered) ------------------
__global__ void k_out(float* __restrict__ out) {
    int idx = blockIdx.x * blockDim.x + threadIdx.x;
    if (idx >= Bn * Cn * Hn * Wn) return;
    int X = idx & 127;
    int Y = (idx >> 7) & 127;
    int c = (idx >> 14) & 127;
    int b = idx >> 21;
    int i0 = (Y + 1) & 1, j0 = (X + 1) & 1;
    float acc = 0.0f;
    #pragma unroll
    for (int a = 0; a < 2; a++) {
        int i = i0 + 2 * a;
        int qy = (Y + 1 - i) >> 1;
        if (qy < 0 || qy >= HR) continue;
        #pragma unroll
        for (int e = 0; e < 2; e++) {
            int j = j0 + 2 * e;
            int qx = (X + 1 - j) >> 1;
            if (qx < 0 || qx >= HR) continue;
            acc += g_M2[b][(c << 4) + (i << 2) + j][(qy << 6) + qx];
        }
    }
    out[idx] = 0.25f * acc;
}

// ---------------------------------------------------------------------------
extern "C" void kernel_launch(void* const* d_in, const int* in_sizes, int n_in,
                              void* d_out, int out_size) {
    const float* x    = (const float*)d_in[0];
    const float* mask = (const float*)d_in[1];
    if (n_in >= 2 && in_sizes[0] < in_sizes[1]) {   // defensive: x is the big one
        const float* t = x; x = mask; mask = t;
    }
    float* out = (float*)d_out;

    k_build_xr<<<(Bn * KC * Ln) / 256, 256>>>(x);
    k_build_vt<<<(Bn * F2 * Ln) / 256, 256>>>(x);
    k_mfilt   <<<(Bn * Ln) / 256, 256>>>(mask);

    k_gemm_G  <<<dim3(Ln / 128, Ln / 128, Bn), 256>>>();
    k_diag    <<<(Bn * Ln) / 256, 256>>>();
    k_scores  <<<dim3(Ln / 256, Ln, Bn), 256>>>();

    k_soft1   <<<dim3(Ln / 256, PCH, Bn), 256>>>();
    k_soft2   <<<(Bn * Ln) / 256, 256>>>();
    k_soft3   <<<dim3(Ln / 256, Ln, Bn), 256>>>();

    k_gemm2   <<<dim3(Ln / 128, F2 / 128, Bn), 256>>>();
    k_out     <<<(Bn * Cn * Hn * Wn) / 256, 256>>>(out);
}

// round 3
// speedup vs baseline: 5.8353x; 5.8353x over previous
#include <cuda_runtime.h>
#include <math.h>

// ---------------------------------------------------------------------------
// ContextualAttention: B=2, C=128, H=W=128, RATE=2, BLOCK=3, SCALE=10, EPS=1e-4
//
// Round 3 (resubmit of untested Round 2 after infra flake):
// dense GEMM-2 (Vt @ att, 137 GFLOP) replaced with an exact sparse
// evaluation. att columns are softmax outputs where everything with
// (score - colmax) <= -21 is flushed to exactly 0 (validated rel_err==0.0 in
// Round 1). Typical nnz/column == 1. We emit per-column nonzero lists in the
// softmax pass and do an SpMM gather; a dense per-column fallback (reading the
// still-materialized dense att in g_S) guarantees correctness if a column
// overflows the sparse cap.
// ---------------------------------------------------------------------------

constexpr int Bn = 2, Cn = 128, Hn = 128, Wn = 128;
constexpr int HR = 64, Ln = 4096, F2 = 2048, KC = 128;
constexpr int PCH = 8;                 // p-chunks for partial softmax
constexpr int PCS = Ln / PCH;          // 512
constexpr int CAP = 128;               // sparse cap per column

// -------- static scratch (allocation-free rule) ----------------------------
__device__ float g_Xr [Bn][KC][Ln];    //   4 MB  (c,p) strided pixels
__device__ float g_Vt [Bn][Ln][F2];    //  67 MB  (p,f) 4x4xC patches
__device__ float g_G  [Bn][Ln][Ln];    // 134 MB  Gram
__device__ float g_S  [Bn][Ln][Ln];    // 134 MB  scores -> att (dense fallback)
__device__ float g_M2 [Bn][Ln][F2];    //  67 MB  (q,f)
__device__ float g_invd [Bn][Ln];
__device__ float g_mfilt[Bn][Ln];
__device__ float g_pmax[Bn][PCH][Ln];
__device__ float g_psum[Bn][PCH][Ln];
__device__ float g_cmax[Bn][Ln];
__device__ float g_crcp[Bn][Ln];
__device__ int   g_cnt [Bn][Ln];
__device__ int   g_sp_p[Bn][Ln][CAP];
__device__ float g_sp_w[Bn][Ln][CAP];

// ---------------------------------------------------------------------------
__global__ void k_build_xr(const float* __restrict__ x) {
    int idx = blockIdx.x * blockDim.x + threadIdx.x;
    if (idx >= Bn * KC * Ln) return;
    int p = idx & (Ln - 1);
    int c = (idx >> 12) & (KC - 1);
    int b = idx >> 19;
    int py = p >> 6, px = p & 63;
    g_Xr[b][c][p] = x[((b * Cn + c) * Hn + 2 * py) * Wn + 2 * px];
}

__global__ void k_build_vt(const float* __restrict__ x) {
    int idx = blockIdx.x * blockDim.x + threadIdx.x;
    if (idx >= Bn * Ln * F2) return;
    int f = idx & (F2 - 1);
    int p = (idx >> 11) & (Ln - 1);
    int b = idx >> 23;
    int c = f >> 4, i = (f >> 2) & 3, j = f & 3;
    int py = p >> 6, px = p & 63;
    int r  = 2 * py - 1 + i;
    int cc = 2 * px - 1 + j;
    float v = 0.0f;
    if (r >= 0 && r < Hn && cc >= 0 && cc < Wn)
        v = x[((b * Cn + c) * Hn + r) * Wn + cc];
    g_Vt[b][p][f] = v;
}

__global__ void k_mfilt(const float* __restrict__ mask) {
    int idx = blockIdx.x * blockDim.x + threadIdx.x;
    if (idx >= Bn * Ln) return;
    int q = idx & (Ln - 1);
    int b = idx >> 12;
    g_cnt[b][q] = 0;                    // reset sparse counters every launch
    int qy = q >> 6, qx = q & 63;
    float s = 0.0f;
    #pragma unroll
    for (int dy = -1; dy <= 1; dy++)
        #pragma unroll
        for (int dx = -1; dx <= 1; dx++) {
            int yy = qy + dy, xx = qx + dx;
            if (yy >= 0 && yy < HR && xx >= 0 && xx < HR)
                s += mask[(b * Hn + 2 * yy) * Wn + 2 * xx];
        }
    g_mfilt[b][q] = ((s / 9.0f) == 0.0f) ? 1.0f : 0.0f;
}

// -------- GEMM 1: G = Xr^T * Xr  (both operands k-major, K=128) ------------
__global__ void __launch_bounds__(256) k_gemm_G() {
    int b  = blockIdx.z;
    int m0 = blockIdx.y << 7, n0 = blockIdx.x << 7;
    __shared__ float As[8][128];
    __shared__ float Bs[8][128];
    int tid = threadIdx.x, ty = tid >> 4, tx = tid & 15;
    int lk = tid >> 5, ls = (tid & 31) << 2;
    const float* A = &g_Xr[b][0][0];

    float acc[8][8];
    #pragma unroll
    for (int i = 0; i < 8; i++)
        #pragma unroll
        for (int j = 0; j < 8; j++) acc[i][j] = 0.0f;

    for (int k0 = 0; k0 < KC; k0 += 8) {
        *(float4*)&As[lk][ls] = *(const float4*)&A[(k0 + lk) * Ln + m0 + ls];
        *(float4*)&Bs[lk][ls] = *(const float4*)&A[(k0 + lk) * Ln + n0 + ls];
        __syncthreads();
        #pragma unroll
        for (int kk = 0; kk < 8; kk++) {
            float a[8], bb[8];
            *(float4*)&a[0]  = *(float4*)&As[kk][ty << 2];
            *(float4*)&a[4]  = *(float4*)&As[kk][64 + (ty << 2)];
            *(float4*)&bb[0] = *(float4*)&Bs[kk][tx << 2];
            *(float4*)&bb[4] = *(float4*)&Bs[kk][64 + (tx << 2)];
            #pragma unroll
            for (int i = 0; i < 8; i++)
                #pragma unroll
                for (int j = 0; j < 8; j++) acc[i][j] += a[i] * bb[j];
        }
        __syncthreads();
    }
    #pragma unroll
    for (int i = 0; i < 8; i++) {
        int m = m0 + ((i < 4) ? (ty << 2) + i : 64 + (ty << 2) + i - 4);
        float4 c0 = make_float4(acc[i][0], acc[i][1], acc[i][2], acc[i][3]);
        float4 c1 = make_float4(acc[i][4], acc[i][5], acc[i][6], acc[i][7]);
        *(float4*)&g_G[b][m][n0 + (tx << 2)]      = c0;
        *(float4*)&g_G[b][m][n0 + 64 + (tx << 2)] = c1;
    }
}

// -------- denom from diag of shifted G -------------------------------------
__global__ void k_diag() {
    int idx = blockIdx.x * blockDim.x + threadIdx.x;
    if (idx >= Bn * Ln) return;
    int p = idx & (Ln - 1);
    int b = idx >> 12;
    int py = p >> 6, px = p & 63;
    float acc = 0.0f;
    #pragma unroll
    for (int dy = -1; dy <= 1; dy++)
        #pragma unroll
        for (int dx = -1; dx <= 1; dx++) {
            int yy = py + dy, xx = px + dx;
            if (yy >= 0 && yy < HR && xx >= 0 && xx < HR) {
                int u = (yy << 6) + xx;
                acc += g_G[b][u][u];
            }
        }
    g_invd[b][p] = 10.0f / sqrtf(acc + 0.1152f);   // 1152 * 1e-4
}

// -------- scores: 9-tap diagonal shift-sum of G ----------------------------
__global__ void k_scores() {
    int b = blockIdx.z;
    int p = blockIdx.y;
    int q = (blockIdx.x << 8) + threadIdx.x;
    int py = p >> 6, px = p & 63;
    int qy = q >> 6, qx = q & 63;
    float acc = 0.0f;
    #pragma unroll
    for (int dy = -1; dy <= 1; dy++)
        #pragma unroll
        for (int dx = -1; dx <= 1; dx++) {
            bool ok = (py + dy >= 0) && (py + dy < HR) && (px + dx >= 0) && (px + dx < HR)
                   && (qy + dy >= 0) && (qy + dy < HR) && (qx + dx >= 0) && (qx + dx < HR);
            if (ok) {
                int off = dy * 64 + dx;
                acc += g_G[b][p + off][q + off];
            }
        }
    g_S[b][p][q] = g_mfilt[b][p] * g_invd[b][p] * acc;
}

// -------- softmax over p (columns), chunked --------------------------------
__global__ void k_soft1() {
    int b = blockIdx.z;
    int q = (blockIdx.x << 8) + threadIdx.x;
    int p0 = blockIdx.y * PCS;
    float m = -3.0e38f;
    for (int p = p0; p < p0 + PCS; p++) m = fmaxf(m, g_S[b][p][q]);
    float s = 0.0f;
    for (int p = p0; p < p0 + PCS; p++) {
        float d = g_S[b][p][q] - m;
        if (d > -21.0f) s += __expf(d);   // exp(-21) ~ 7.6e-10: negligible mass
    }
    g_pmax[b][blockIdx.y][q] = m;
    g_psum[b][blockIdx.y][q] = s;
}

__global__ void k_soft2() {
    int idx = blockIdx.x * blockDim.x + threadIdx.x;
    if (idx >= Bn * Ln) return;
    int q = idx & (Ln - 1);
    int b = idx >> 12;
    float m = -3.0e38f;
    #pragma unroll
    for (int ch = 0; ch < PCH; ch++) m = fmaxf(m, g_pmax[b][ch][q]);
    float s = 0.0f;
    #pragma unroll
    for (int ch = 0; ch < PCH; ch++) s += g_psum[b][ch][q] * __expf(g_pmax[b][ch][q] - m);
    g_cmax[b][q] = m;
    g_crcp[b][q] = 1.0f / s;
}

// final softmax + sparse emission
__global__ void k_soft3() {
    int b = blockIdx.z;
    int p = blockIdx.y;
    int q = (blockIdx.x << 8) + threadIdx.x;
    float d = g_S[b][p][q] - g_cmax[b][q];
    float w = 0.0f;
    if (d > -21.0f) w = __expf(d) * g_crcp[b][q];
    w *= g_mfilt[b][p];
    g_S[b][p][q] = w;                     // dense copy (overflow fallback)
    if (w != 0.0f) {
        int slot = atomicAdd(&g_cnt[b][q], 1);
        if (slot < CAP) {
            g_sp_p[b][q][slot] = p;
            g_sp_w[b][q][slot] = w;
        }
    }
}

// -------- SpMM: M2[q][:] = sum_k w_k * Vt[p_k][:] --------------------------
__global__ void __launch_bounds__(256) k_spmm() {
    int q = blockIdx.x, b = blockIdx.y;
    int tid = threadIdx.x;
    __shared__ int   s_p[CAP];
    __shared__ float s_w[CAP];
    int cnt = g_cnt[b][q];

    float acc[8];
    #pragma unroll
    for (int i = 0; i < 8; i++) acc[i] = 0.0f;

    if (cnt <= CAP) {
        if (tid < cnt) { s_p[tid] = g_sp_p[b][q][tid]; s_w[tid] = g_sp_w[b][q][tid]; }
        __syncthreads();
        if (tid == 0 && cnt > 1) {        // deterministic order: sort by p
            for (int i = 1; i < cnt; i++) {
                int   kp = s_p[i]; float kw = s_w[i];
                int j = i - 1;
                while (j >= 0 && s_p[j] > kp) { s_p[j+1] = s_p[j]; s_w[j+1] = s_w[j]; j--; }
                s_p[j+1] = kp; s_w[j+1] = kw;
            }
        }
        __syncthreads();
        for (int k = 0; k < cnt; k++) {
            float w = s_w[k];
            const float* v = &g_Vt[b][s_p[k]][0];
            #pragma unroll
            for (int i = 0; i < 8; i++) acc[i] += w * v[tid + (i << 8)];
        }
    } else {
        // dense fallback (never hit for this input; keeps kernel exact always)
        for (int p = 0; p < Ln; p++) {
            float w = g_S[b][p][q];
            if (w != 0.0f) {
                const float* v = &g_Vt[b][p][0];
                #pragma unroll
                for (int i = 0; i < 8; i++) acc[i] += w * v[tid + (i << 8)];
            }
        }
    }
    #pragma unroll
    for (int i = 0; i < 8; i++) g_M2[b][q][tid + (i << 8)] = acc[i];
}

// -------- overlap-add (transposed-conv scatter, gathered) ------------------
__global__ void k_out(float* __restrict__ out) {
    int idx = blockIdx.x * blockDim.x + threadIdx.x;
    if (idx >= Bn * Cn * Hn * Wn) return;
    int X = idx & 127;
    int Y = (idx >> 7) & 127;
    int c = (idx >> 14) & 127;
    int b = idx >> 21;
    int i0 = (Y + 1) & 1, j0 = (X + 1) & 1;
    float acc = 0.0f;
    #pragma unroll
    for (int a = 0; a < 2; a++) {
        int i = i0 + 2 * a;
        int qy = (Y + 1 - i) >> 1;
        if (qy < 0 || qy >= HR) continue;
        #pragma unroll
        for (int e = 0; e < 2; e++) {
            int j = j0 + 2 * e;
            int qx = (X + 1 - j) >> 1;
            if (qx < 0 || qx >= HR) continue;
            acc += g_M2[b][(qy << 6) + qx][(c << 4) + (i << 2) + j];
        }
    }
    out[idx] = 0.25f * acc;
}

// ---------------------------------------------------------------------------
extern "C" void kernel_launch(void* const* d_in, const int* in_sizes, int n_in,
                              void* d_out, int out_size) {
    const float* x    = (const float*)d_in[0];
    const float* mask = (const float*)d_in[1];
    if (n_in >= 2 && in_sizes[0] < in_sizes[1]) {   // defensive: x is the big one
        const float* t = x; x = mask; mask = t;
    }
    float* out = (float*)d_out;

    k_build_xr<<<(Bn * KC * Ln) / 256, 256>>>(x);
    k_build_vt<<<(Bn * Ln * F2) / 256, 256>>>(x);
    k_mfilt   <<<(Bn * Ln) / 256, 256>>>(mask);

    k_gemm_G  <<<dim3(Ln / 128, Ln / 128, Bn), 256>>>();
    k_diag    <<<(Bn * Ln) / 256, 256>>>();
    k_scores  <<<dim3(Ln / 256, Ln, Bn), 256>>>();

    k_soft1   <<<dim3(Ln / 256, PCH, Bn), 256>>>();
    k_soft2   <<<(Bn * Ln) / 256, 256>>>();
    k_soft3   <<<dim3(Ln / 256, Ln, Bn), 256>>>();

    k_spmm    <<<dim3(Ln, Bn), 256>>>();
    k_out     <<<(Bn * Cn * Hn * Wn) / 256, 256>>>(out);
}